// round 6
// baseline (speedup 1.0000x reference)
#include <cuda_runtime.h>
#include <math.h>
#include <stdint.h>

#define Bb 2
#define Ss 1024
#define Tt 2048
#define Dd 2048
#define Ll 4
#define NE 16
#define Hh 16
#define DHh 128
#define CAPe 153

typedef unsigned long long u64;

// ---------------- packed f32x2 helpers --------------------------------------
__device__ __forceinline__ void ffma2(u64& d, u64 a, u64 b) {
    asm("fma.rn.f32x2 %0, %1, %2, %0;" : "+l"(d) : "l"(a), "l"(b));
}
__device__ __forceinline__ u64 fmul2(u64 a, u64 b) {
    u64 r; asm("mul.rn.f32x2 %0, %1, %2;" : "=l"(r) : "l"(a), "l"(b)); return r;
}
__device__ __forceinline__ u64 pk2(float x, float y) {
    u64 r; asm("mov.b64 %0, {%1, %2};" : "=l"(r) : "f"(x), "f"(y)); return r;
}
__device__ __forceinline__ void upk2(u64 v, float& x, float& y) {
    asm("mov.b64 {%0, %1}, %2;" : "=f"(x), "=f"(y) : "l"(v));
}

// ---------------- tf32 / mma helpers ----------------------------------------
__device__ __forceinline__ float tf32r(float x) {
    uint32_t u; asm("cvt.rna.tf32.f32 %0, %1;" : "=r"(u) : "f"(x));
    return __uint_as_float(u);
}
__device__ __forceinline__ void mma8(float* d, const uint32_t* a, const uint32_t* b) {
    asm volatile(
        "mma.sync.aligned.m16n8k8.row.col.f32.tf32.tf32.f32 "
        "{%0,%1,%2,%3}, {%4,%5,%6,%7}, {%8,%9}, {%0,%1,%2,%3};"
        : "+f"(d[0]), "+f"(d[1]), "+f"(d[2]), "+f"(d[3])
        : "r"(a[0]), "r"(a[1]), "r"(a[2]), "r"(a[3]), "r"(b[0]), "r"(b[1]));
}
__device__ __forceinline__ uint32_t smem_u32(const void* p) {
    uint32_t a;
    asm("{ .reg .u64 t; cvta.to.shared.u64 t, %1; cvt.u32.u64 %0, t; }" : "=r"(a) : "l"(p));
    return a;
}
__device__ __forceinline__ void cpa16(uint32_t dst, const void* src) {
    asm volatile("cp.async.ca.shared.global [%0], [%1], 16;" :: "r"(dst), "l"(src));
}
__device__ __forceinline__ void cpa_commit() { asm volatile("cp.async.commit_group;" ::: "memory"); }
template<int N_> __device__ __forceinline__ void cpa_wait() {
    asm volatile("cp.async.wait_group %0;" :: "n"(N_) : "memory");
}

// smem: 2 stages x 4 tiles(A_hi A_lo B_hi B_lo) x 128 rows x 20 floats
#define ROWSTR   20
#define TILE_F   (128 * ROWSTR)         // 2560 floats
#define TILE_B   (TILE_F * 4)           // 10240 bytes
#define STAGE_F  (TILE_F * 4)           // 10240 floats
#define STAGE_B  (STAGE_F * 4)          // 40960 bytes
#define GEMM_SMEM (2 * STAGE_B)         // 81920 bytes

// ---------------- scratch (static device globals) ---------------------------
__device__ float g_x[Tt * Dd];
__device__ float g_xn[Tt * Dd];
__device__ float g_xn_hi[Tt * Dd];
__device__ float g_xn_lo[Tt * Dd];
__device__ float g_qkv[Tt * 3 * Dd];
__device__ float g_at_hi[Tt * Dd];
__device__ float g_at_lo[Tt * Dd];
__device__ float g_wq_hi[3 * Dd * Dd];
__device__ float g_wq_lo[3 * Dd * Dd];
__device__ float g_wo_hi[Dd * Dd];
__device__ float g_wo_lo[Dd * Dd];
__device__ float g_we_hi[NE * Dd * Dd];
__device__ float g_we_lo[NE * Dd * Dd];
__device__ int   g_expert[Tt];
__device__ float g_prob[Tt];
__device__ float g_probsum[NE];
__device__ int   g_tok[NE * CAPe];
__device__ int   g_cnt[NE];
__device__ float g_aux;

__global__ void k_init() { g_aux = 0.0f; }
__global__ void k_zero16() { if (threadIdx.x < NE) g_probsum[threadIdx.x] = 0.0f; }

// ---------------- weight split ----------------------------------------------
__global__ void k_wsplit(const float4* __restrict__ src, float4* __restrict__ hi,
                         float4* __restrict__ lo, int n4) {
    int i = blockIdx.x * 256 + threadIdx.x;
    if (i < n4) {
        float4 v = src[i];
        float4 h, l;
        h.x = tf32r(v.x); l.x = tf32r(v.x - h.x);
        h.y = tf32r(v.y); l.y = tf32r(v.y - h.y);
        h.z = tf32r(v.z); l.z = tf32r(v.z - h.z);
        h.w = tf32r(v.w); l.w = tf32r(v.w - h.w);
        hi[i] = h; lo[i] = l;
    }
}

// ---------------- embedding gather ------------------------------------------
__global__ void k_embed(const int* __restrict__ tokens, const float* __restrict__ emb) {
    int idx = blockIdx.x * 256 + threadIdx.x;
    int t = idx / Dd;
    int d = idx % Dd;
    g_x[idx] = emb[(size_t)tokens[t] * Dd + d];
}

// ---------------- layernorm (writes fp32 + tf32 hi/lo splits) ----------------
__global__ void k_ln(const float* __restrict__ gamma, const float* __restrict__ beta) {
    int t = blockIdx.x;
    const float* row = g_x + (size_t)t * Dd;
    float s = 0.f, s2 = 0.f;
    for (int d = threadIdx.x; d < Dd; d += 256) {
        float v = row[d];
        s += v; s2 += v * v;
    }
    #pragma unroll
    for (int o = 16; o; o >>= 1) {
        s  += __shfl_xor_sync(0xffffffffu, s, o);
        s2 += __shfl_xor_sync(0xffffffffu, s2, o);
    }
    __shared__ float shs[8], shs2[8];
    __shared__ float smu, srstd;
    int w = threadIdx.x >> 5, ln = threadIdx.x & 31;
    if (ln == 0) { shs[w] = s; shs2[w] = s2; }
    __syncthreads();
    if (threadIdx.x == 0) {
        float a = 0.f, b2 = 0.f;
        #pragma unroll
        for (int i = 0; i < 8; i++) { a += shs[i]; b2 += shs2[i]; }
        float m = a / (float)Dd;
        float var = b2 / (float)Dd - m * m;
        smu = m;
        srstd = rsqrtf(var + 1e-5f);
    }
    __syncthreads();
    float mu = smu, rstd = srstd;
    for (int d = threadIdx.x; d < Dd; d += 256) {
        float v = (row[d] - mu) * rstd * gamma[d] + beta[d];
        size_t o = (size_t)t * Dd + d;
        g_xn[o] = v;
        float h = tf32r(v);
        g_xn_hi[o] = h;
        g_xn_lo[o] = tf32r(v - h);
    }
}

// ---------------- mma mainloop pieces ---------------------------------------
// per-chunk compute: BK=16, warp tile 32x64, 3-term split
__device__ __forceinline__ void mma_chunk16(const float* smf, int wr, int wc,
                                            int grp, int qid, float acc[2][8][4]) {
    #pragma unroll
    for (int ks = 0; ks < 16; ks += 8) {
        uint32_t ah[2][4], al[2][4];
        #pragma unroll
        for (int mi = 0; mi < 2; mi++) {
            int b0 = (wr * 32 + mi * 16 + grp) * ROWSTR + ks + qid;
            int b1 = b0 + 8 * ROWSTR;
            ah[mi][0] = __float_as_uint(smf[b0]);
            ah[mi][1] = __float_as_uint(smf[b1]);
            ah[mi][2] = __float_as_uint(smf[b0 + 4]);
            ah[mi][3] = __float_as_uint(smf[b1 + 4]);
            al[mi][0] = __float_as_uint(smf[TILE_F + b0]);
            al[mi][1] = __float_as_uint(smf[TILE_F + b1]);
            al[mi][2] = __float_as_uint(smf[TILE_F + b0 + 4]);
            al[mi][3] = __float_as_uint(smf[TILE_F + b1 + 4]);
        }
        #pragma unroll
        for (int ni = 0; ni < 8; ni++) {
            int c0 = (wc * 64 + ni * 8 + grp) * ROWSTR + ks + qid;
            uint32_t bh[2], bl[2];
            bh[0] = __float_as_uint(smf[2 * TILE_F + c0]);
            bh[1] = __float_as_uint(smf[2 * TILE_F + c0 + 4]);
            bl[0] = __float_as_uint(smf[3 * TILE_F + c0]);
            bl[1] = __float_as_uint(smf[3 * TILE_F + c0 + 4]);
            #pragma unroll
            for (int mi = 0; mi < 2; mi++) {
                mma8(acc[mi][ni], ah[mi], bh);
                mma8(acc[mi][ni], ah[mi], bl);
                mma8(acc[mi][ni], al[mi], bh);
            }
        }
    }
}

// ---------------- dense GEMM: C[M,N] = A @ W^T + bias (+res) ----------------
// BM=128, BN=128, BK=16, 256 threads, pre-split tf32 inputs, cp.async x2 stage
__global__ void __launch_bounds__(256, 2)
k_gemm_mma(const float* __restrict__ Ahi, const float* __restrict__ Alo,
           const float* __restrict__ Bhi, const float* __restrict__ Blo,
           const float* __restrict__ bias, const float* __restrict__ res,
           float* __restrict__ C, int N, int K) {
    extern __shared__ float sm[];
    uint32_t sb = smem_u32(sm);
    int tid = threadIdx.x, wid = tid >> 5, lane = tid & 31;
    int grp = lane >> 2, qid = lane & 3;
    int wr = wid & 3, wc = wid >> 2;
    int bm = blockIdx.y * 128, bn = blockIdx.x * 128;

    // copy slots: tile is 128 rows x 16 floats = 512 x 16B; thread does 2 per tile
    int i0 = tid, i1 = tid + 256;
    int r0 = i0 >> 2, c0 = (i0 & 3) << 2;
    int r1 = i1 >> 2, c1 = (i1 & 3) << 2;
    uint32_t sa0 = (uint32_t)(r0 * ROWSTR + c0) * 4;
    uint32_t sa1 = (uint32_t)(r1 * ROWSTR + c1) * 4;
    const float* pAh0 = Ahi + (size_t)(bm + r0) * K + c0;
    const float* pAh1 = Ahi + (size_t)(bm + r1) * K + c1;
    const float* pAl0 = Alo + (size_t)(bm + r0) * K + c0;
    const float* pAl1 = Alo + (size_t)(bm + r1) * K + c1;
    const float* pBh0 = Bhi + (size_t)(bn + r0) * K + c0;
    const float* pBh1 = Bhi + (size_t)(bn + r1) * K + c1;
    const float* pBl0 = Blo + (size_t)(bn + r0) * K + c0;
    const float* pBl1 = Blo + (size_t)(bn + r1) * K + c1;

    float acc[2][8][4];
    #pragma unroll
    for (int mi = 0; mi < 2; mi++)
        #pragma unroll
        for (int ni = 0; ni < 8; ni++)
            #pragma unroll
            for (int j = 0; j < 4; j++) acc[mi][ni][j] = 0.f;

    int nch = K / 16;
    // prologue: issue chunk 0
    {
        uint32_t b = sb;
        cpa16(b + sa0, pAh0); cpa16(b + sa1, pAh1);
        cpa16(b + TILE_B + sa0, pAl0); cpa16(b + TILE_B + sa1, pAl1);
        cpa16(b + 2 * TILE_B + sa0, pBh0); cpa16(b + 2 * TILE_B + sa1, pBh1);
        cpa16(b + 3 * TILE_B + sa0, pBl0); cpa16(b + 3 * TILE_B + sa1, pBl1);
        cpa_commit();
    }
    for (int c = 0; c < nch; c++) {
        if (c + 1 < nch) {
            uint32_t b = sb + ((c + 1) & 1) * STAGE_B;
            int k0 = (c + 1) * 16;
            cpa16(b + sa0, pAh0 + k0); cpa16(b + sa1, pAh1 + k0);
            cpa16(b + TILE_B + sa0, pAl0 + k0); cpa16(b + TILE_B + sa1, pAl1 + k0);
            cpa16(b + 2 * TILE_B + sa0, pBh0 + k0); cpa16(b + 2 * TILE_B + sa1, pBh1 + k0);
            cpa16(b + 3 * TILE_B + sa0, pBl0 + k0); cpa16(b + 3 * TILE_B + sa1, pBl1 + k0);
            cpa_commit();
            cpa_wait<1>();
        } else {
            cpa_wait<0>();
        }
        __syncthreads();
        mma_chunk16(sm + (c & 1) * STAGE_F, wr, wc, grp, qid, acc);
        __syncthreads();
    }

    #pragma unroll
    for (int mi = 0; mi < 2; mi++) {
        int r0o = bm + wr * 32 + mi * 16 + grp;
        int r1o = r0o + 8;
        #pragma unroll
        for (int ni = 0; ni < 8; ni++) {
            int cc = bn + wc * 64 + ni * 8 + qid * 2;
            float b0 = bias[cc], b1 = bias[cc + 1];
            float v0 = acc[mi][ni][0] + b0, v1 = acc[mi][ni][1] + b1;
            float v2 = acc[mi][ni][2] + b0, v3 = acc[mi][ni][3] + b1;
            if (res) {
                v0 += res[(size_t)r0o * N + cc];
                v1 += res[(size_t)r0o * N + cc + 1];
                v2 += res[(size_t)r1o * N + cc];
                v3 += res[(size_t)r1o * N + cc + 1];
            }
            C[(size_t)r0o * N + cc]     = v0;
            C[(size_t)r0o * N + cc + 1] = v1;
            C[(size_t)r1o * N + cc]     = v2;
            C[(size_t)r1o * N + cc + 1] = v3;
        }
    }
}

// ---------------- MoE GEMM: x[t] += p*(h[t] @ We^T + be) --------------------
__global__ void __launch_bounds__(256, 2)
k_moe_mma(const float* __restrict__ b_exp) {
    int e = blockIdx.z;
    int cnt = g_cnt[e];
    int row0 = blockIdx.y * 128;
    if (row0 >= cnt) return;
    int bn = blockIdx.x * 128;

    extern __shared__ float sm[];
    __shared__ int   toks[128];
    __shared__ float pb[128];
    uint32_t sb = smem_u32(sm);
    int tid = threadIdx.x, wid = tid >> 5, lane = tid & 31;
    int grp = lane >> 2, qid = lane & 3;
    int wr = wid & 3, wc = wid >> 2;

    if (tid < 128) {
        int s = row0 + tid;
        if (s < cnt) {
            int t = g_tok[e * CAPe + s];
            toks[tid] = t;
            pb[tid] = g_prob[t];
        } else {
            toks[tid] = 0;       // valid row; output discarded
            pb[tid] = 0.f;
        }
    }
    __syncthreads();

    int i0 = tid, i1 = tid + 256;
    int r0 = i0 >> 2, c0 = (i0 & 3) << 2;
    int r1 = i1 >> 2, c1 = (i1 & 3) << 2;
    uint32_t sa0 = (uint32_t)(r0 * ROWSTR + c0) * 4;
    uint32_t sa1 = (uint32_t)(r1 * ROWSTR + c1) * 4;
    int t0 = toks[r0], t1 = toks[r1];
    const float* pAh0 = g_xn_hi + (size_t)t0 * Dd + c0;
    const float* pAh1 = g_xn_hi + (size_t)t1 * Dd + c1;
    const float* pAl0 = g_xn_lo + (size_t)t0 * Dd + c0;
    const float* pAl1 = g_xn_lo + (size_t)t1 * Dd + c1;
    const float* Wh = g_we_hi + (size_t)e * Dd * Dd + (size_t)bn * Dd;
    const float* Wl = g_we_lo + (size_t)e * Dd * Dd + (size_t)bn * Dd;
    const float* pBh0 = Wh + (size_t)r0 * Dd + c0;
    const float* pBh1 = Wh + (size_t)r1 * Dd + c1;
    const float* pBl0 = Wl + (size_t)r0 * Dd + c0;
    const float* pBl1 = Wl + (size_t)r1 * Dd + c1;

    float acc[2][8][4];
    #pragma unroll
    for (int mi = 0; mi < 2; mi++)
        #pragma unroll
        for (int ni = 0; ni < 8; ni++)
            #pragma unroll
            for (int j = 0; j < 4; j++) acc[mi][ni][j] = 0.f;

    const int nch = Dd / 16;
    {
        uint32_t b = sb;
        cpa16(b + sa0, pAh0); cpa16(b + sa1, pAh1);
        cpa16(b + TILE_B + sa0, pAl0); cpa16(b + TILE_B + sa1, pAl1);
        cpa16(b + 2 * TILE_B + sa0, pBh0); cpa16(b + 2 * TILE_B + sa1, pBh1);
        cpa16(b + 3 * TILE_B + sa0, pBl0); cpa16(b + 3 * TILE_B + sa1, pBl1);
        cpa_commit();
    }
    for (int c = 0; c < nch; c++) {
        if (c + 1 < nch) {
            uint32_t b = sb + ((c + 1) & 1) * STAGE_B;
            int k0 = (c + 1) * 16;
            cpa16(b + sa0, pAh0 + k0); cpa16(b + sa1, pAh1 + k0);
            cpa16(b + TILE_B + sa0, pAl0 + k0); cpa16(b + TILE_B + sa1, pAl1 + k0);
            cpa16(b + 2 * TILE_B + sa0, pBh0 + k0); cpa16(b + 2 * TILE_B + sa1, pBh1 + k0);
            cpa16(b + 3 * TILE_B + sa0, pBl0 + k0); cpa16(b + 3 * TILE_B + sa1, pBl1 + k0);
            cpa_commit();
            cpa_wait<1>();
        } else {
            cpa_wait<0>();
        }
        __syncthreads();
        mma_chunk16(sm + (c & 1) * STAGE_F, wr, wc, grp, qid, acc);
        __syncthreads();
    }

    const float* be = b_exp + (size_t)e * Dd;
    #pragma unroll
    for (int mi = 0; mi < 2; mi++) {
        int lr0 = wr * 32 + mi * 16 + grp;
        int lr1 = lr0 + 8;
        int s0 = row0 + lr0, s1 = row0 + lr1;
        #pragma unroll
        for (int ni = 0; ni < 8; ni++) {
            int cc = bn + wc * 64 + ni * 8 + qid * 2;
            float b0 = be[cc], b1 = be[cc + 1];
            if (s0 < cnt) {
                int t = toks[lr0]; float p = pb[lr0];
                g_x[(size_t)t * Dd + cc]     += p * (acc[mi][ni][0] + b0);
                g_x[(size_t)t * Dd + cc + 1] += p * (acc[mi][ni][1] + b1);
            }
            if (s1 < cnt) {
                int t = toks[lr1]; float p = pb[lr1];
                g_x[(size_t)t * Dd + cc]     += p * (acc[mi][ni][2] + b0);
                g_x[(size_t)t * Dd + cc + 1] += p * (acc[mi][ni][3] + b1);
            }
        }
    }
}

// ---------------- attention (fp32 SIMT, writes tf32 hi/lo) ------------------
__global__ void __launch_bounds__(256, 2) k_attn() {
    int bh = blockIdx.x;
    int b = bh >> 4, h = bh & 15;
    int q0 = blockIdx.y * 32;
    __shared__ float Qs[32][132];
    __shared__ float KVs[32][132];
    __shared__ float Sc[32][36];
    int tid = threadIdx.x;

    #pragma unroll
    for (int j = 0; j < 4; j++) {
        int i = tid + j * 256;
        int r = i >> 5, d4 = (i & 31) << 2;
        float4 v = *(const float4*)&g_qkv[(size_t)(b * Ss + q0 + r) * (3 * Dd) + h * DHh + d4];
        *(float4*)&Qs[r][d4] = v;
    }

    int q  = tid >> 3;
    int dp = tid & 7;
    float m = -1e30f, l = 0.f;
    u64 acc2[8];
    #pragma unroll
    for (int j = 0; j < 8; j++) acc2[j] = 0ULL;

    const float scale = 0.08838834764831845f;

    for (int kb = 0; kb < Ss; kb += 32) {
        __syncthreads();
        #pragma unroll
        for (int j = 0; j < 4; j++) {
            int i = tid + j * 256;
            int r = i >> 5, d4 = (i & 31) << 2;
            float4 v = *(const float4*)&g_qkv[(size_t)(b * Ss + kb + r) * (3 * Dd) + Dd + h * DHh + d4];
            *(float4*)&KVs[r][d4] = v;
        }
        __syncthreads();
        {
            u64 s2[4] = {0ULL, 0ULL, 0ULL, 0ULL};
            #pragma unroll
            for (int ch = 0; ch < 8; ch++) {
                ulonglong2 qa = *(const ulonglong2*)&Qs[q][ch * 16];
                ulonglong2 qb = *(const ulonglong2*)&Qs[q][ch * 16 + 4];
                ulonglong2 qc = *(const ulonglong2*)&Qs[q][ch * 16 + 8];
                ulonglong2 qd = *(const ulonglong2*)&Qs[q][ch * 16 + 12];
                #pragma unroll
                for (int kk = 0; kk < 4; kk++) {
                    int k = dp + kk * 8;
                    ulonglong2 ka = *(const ulonglong2*)&KVs[k][ch * 16];
                    ulonglong2 kb2 = *(const ulonglong2*)&KVs[k][ch * 16 + 4];
                    ulonglong2 kc = *(const ulonglong2*)&KVs[k][ch * 16 + 8];
                    ulonglong2 kd = *(const ulonglong2*)&KVs[k][ch * 16 + 12];
                    ffma2(s2[kk], qa.x, ka.x);
                    ffma2(s2[kk], qa.y, ka.y);
                    ffma2(s2[kk], qb.x, kb2.x);
                    ffma2(s2[kk], qb.y, kb2.y);
                    ffma2(s2[kk], qc.x, kc.x);
                    ffma2(s2[kk], qc.y, kc.y);
                    ffma2(s2[kk], qd.x, kd.x);
                    ffma2(s2[kk], qd.y, kd.y);
                }
            }
            #pragma unroll
            for (int kk = 0; kk < 4; kk++) {
                float lo, hi; upk2(s2[kk], lo, hi);
                Sc[q][dp + kk * 8] = (lo + hi) * scale;
            }
        }
        __syncthreads();
        #pragma unroll
        for (int j = 0; j < 4; j++) {
            int i = tid + j * 256;
            int r = i >> 5, d4 = (i & 31) << 2;
            float4 v = *(const float4*)&g_qkv[(size_t)(b * Ss + kb + r) * (3 * Dd) + 2 * Dd + h * DHh + d4];
            *(float4*)&KVs[r][d4] = v;
        }
        float sc[32];
        #pragma unroll
        for (int k = 0; k < 32; k++) sc[k] = Sc[q][k];
        float mx = -1e30f;
        #pragma unroll
        for (int k = 0; k < 32; k++) mx = fmaxf(mx, sc[k]);
        float nm = fmaxf(m, mx);
        float corr = __expf(m - nm);
        l *= corr;
        u64 cp = pk2(corr, corr);
        #pragma unroll
        for (int j = 0; j < 8; j++) acc2[j] = fmul2(acc2[j], cp);
        float p[32];
        #pragma unroll
        for (int k = 0; k < 32; k++) { p[k] = __expf(sc[k] - nm); l += p[k]; }
        m = nm;
        __syncthreads();
        #pragma unroll
        for (int k = 0; k < 32; k++) {
            u64 pp = pk2(p[k], p[k]);
            ulonglong2 v0 = *(const ulonglong2*)&KVs[k][dp * 16];
            ulonglong2 v1 = *(const ulonglong2*)&KVs[k][dp * 16 + 4];
            ulonglong2 v2 = *(const ulonglong2*)&KVs[k][dp * 16 + 8];
            ulonglong2 v3 = *(const ulonglong2*)&KVs[k][dp * 16 + 12];
            ffma2(acc2[0], pp, v0.x);
            ffma2(acc2[1], pp, v0.y);
            ffma2(acc2[2], pp, v1.x);
            ffma2(acc2[3], pp, v1.y);
            ffma2(acc2[4], pp, v2.x);
            ffma2(acc2[5], pp, v2.y);
            ffma2(acc2[6], pp, v3.x);
            ffma2(acc2[7], pp, v3.y);
        }
    }
    float inv = 1.f / l;
    int t = b * Ss + q0 + q;
    size_t ob = (size_t)t * Dd + h * DHh + dp * 16;
    float o[16];
    upk2(acc2[0], o[0],  o[1]);   upk2(acc2[1], o[2],  o[3]);
    upk2(acc2[2], o[4],  o[5]);   upk2(acc2[3], o[6],  o[7]);
    upk2(acc2[4], o[8],  o[9]);   upk2(acc2[5], o[10], o[11]);
    upk2(acc2[6], o[12], o[13]);  upk2(acc2[7], o[14], o[15]);
    #pragma unroll
    for (int j = 0; j < 16; j++) {
        float v = o[j] * inv;
        float hv = tf32r(v);
        g_at_hi[ob + j] = hv;
        g_at_lo[ob + j] = tf32r(v - hv);
    }
}

// ---------------- gate ------------------------------------------------------
__global__ void k_gate(const float* __restrict__ wg) {
    int warp = threadIdx.x >> 5;
    int lane = threadIdx.x & 31;
    int t = blockIdx.x * 8 + warp;
    __shared__ float bsum[NE];
    if (threadIdx.x < NE) bsum[threadIdx.x] = 0.f;
    __syncthreads();

    float lg[16];
    #pragma unroll
    for (int e = 0; e < 16; e++) lg[e] = 0.f;
    const float* row = g_xn + (size_t)t * Dd;
    for (int d = lane; d < Dd; d += 32) {
        float x = row[d];
        const float* w = wg + (size_t)d * NE;
        #pragma unroll
        for (int e = 0; e < 16; e++) lg[e] += x * w[e];
    }
    #pragma unroll
    for (int e = 0; e < 16; e++)
        #pragma unroll
        for (int o = 16; o; o >>= 1) lg[e] += __shfl_xor_sync(0xffffffffu, lg[e], o);

    float mx = lg[0];
    #pragma unroll
    for (int e = 1; e < 16; e++) mx = fmaxf(mx, lg[e]);
    float pe[16]; float se = 0.f;
    #pragma unroll
    for (int e = 0; e < 16; e++) { pe[e] = __expf(lg[e] - mx); se += pe[e]; }
    float inv = 1.f / se;

    if (lane == 0) {
        int be = 0; float bl = lg[0];
        #pragma unroll
        for (int e = 1; e < 16; e++) if (lg[e] > bl) { bl = lg[e]; be = e; }
        g_expert[t] = be;
        g_prob[t] = pe[be] * inv;
        #pragma unroll
        for (int e = 0; e < 16; e++) atomicAdd(&bsum[e], pe[e] * inv);
    }
    __syncthreads();
    if (threadIdx.x < NE) atomicAdd(&g_probsum[threadIdx.x], bsum[threadIdx.x]);
}

// ---------------- routing ---------------------------------------------------
__global__ void k_route() {
    __shared__ int sh_e[Tt];
    __shared__ int cnts[256][NE];
    __shared__ int tot[NE];
    int tid = threadIdx.x;
    for (int i = tid; i < Tt; i += 256) sh_e[i] = g_expert[i];
    #pragma unroll
    for (int e = 0; e < NE; e++) cnts[tid][e] = 0;
    __syncthreads();
    for (int i = 0; i < 8; i++) {
        int e = sh_e[tid * 8 + i];
        cnts[tid][e]++;
    }
    __syncthreads();
    if (tid < NE) {
        int run = 0;
        for (int i = 0; i < 256; i++) {
            int c = cnts[i][tid];
            cnts[i][tid] = run;
            run += c;
        }
        tot[tid] = run;
        g_cnt[tid] = (run < CAPe) ? run : CAPe;
    }
    __syncthreads();
    for (int i = 0; i < 8; i++) {
        int t = tid * 8 + i;
        int e = sh_e[t];
        int r = cnts[tid][e]++;
        if (r < CAPe) g_tok[e * CAPe + r] = t;
    }
    if (tid == 0) {
        float a = 0.f;
        for (int e = 0; e < NE; e++) a += (float)tot[e] * g_probsum[e];
        g_aux += a * ((float)NE / ((float)Tt * (float)Tt));
    }
}

// ---------------- output ----------------------------------------------------
__global__ void k_out(float* __restrict__ out, int n) {
    int idx = blockIdx.x * 256 + threadIdx.x;
    if (idx < n) {
        if (idx < Tt * Dd) out[idx] = g_x[idx];
        else out[idx] = g_aux;
    }
}

// ---------------- launch ----------------------------------------------------
extern "C" void kernel_launch(void* const* d_in, const int* in_sizes, int n_in,
                              void* d_out, int out_size) {
    const int*   tokens = (const int*)d_in[0];
    const float* emb    = (const float*)d_in[1];
    const float* w_qkv  = (const float*)d_in[2];
    const float* b_qkv  = (const float*)d_in[3];
    const float* w_out  = (const float*)d_in[4];
    const float* b_out  = (const float*)d_in[5];
    const float* attn_g = (const float*)d_in[6];
    const float* attn_b = (const float*)d_in[7];
    const float* moe_g  = (const float*)d_in[8];
    const float* moe_b  = (const float*)d_in[9];
    const float* w_gate = (const float*)d_in[10];
    const float* w_exp  = (const float*)d_in[11];
    const float* b_exp  = (const float*)d_in[12];

    float *pqkv, *px;
    cudaGetSymbolAddress((void**)&px, g_x);
    cudaGetSymbolAddress((void**)&pqkv, g_qkv);
    float *pxnh, *pxnl, *path, *patl;
    cudaGetSymbolAddress((void**)&pxnh, g_xn_hi);
    cudaGetSymbolAddress((void**)&pxnl, g_xn_lo);
    cudaGetSymbolAddress((void**)&path, g_at_hi);
    cudaGetSymbolAddress((void**)&patl, g_at_lo);
    float *pwqh, *pwql, *pwoh, *pwol, *pweh, *pwel;
    cudaGetSymbolAddress((void**)&pwqh, g_wq_hi);
    cudaGetSymbolAddress((void**)&pwql, g_wq_lo);
    cudaGetSymbolAddress((void**)&pwoh, g_wo_hi);
    cudaGetSymbolAddress((void**)&pwol, g_wo_lo);
    cudaGetSymbolAddress((void**)&pweh, g_we_hi);
    cudaGetSymbolAddress((void**)&pwel, g_we_lo);

    cudaFuncSetAttribute(k_gemm_mma, cudaFuncAttributeMaxDynamicSharedMemorySize, GEMM_SMEM);
    cudaFuncSetAttribute(k_moe_mma, cudaFuncAttributeMaxDynamicSharedMemorySize, GEMM_SMEM);

    k_init<<<1, 1>>>();
    // one-time weight splits (per replay; deterministic)
    {
        int n4 = 3 * Dd * Dd / 4;
        k_wsplit<<<(n4 + 255) / 256, 256>>>((const float4*)w_qkv, (float4*)pwqh, (float4*)pwql, n4);
        n4 = Dd * Dd / 4;
        k_wsplit<<<(n4 + 255) / 256, 256>>>((const float4*)w_out, (float4*)pwoh, (float4*)pwol, n4);
        n4 = NE * Dd * Dd / 4;
        k_wsplit<<<(n4 + 255) / 256, 256>>>((const float4*)w_exp, (float4*)pweh, (float4*)pwel, n4);
    }
    k_embed<<<(Tt * Dd) / 256, 256>>>(tokens, emb);

    for (int l = 0; l < Ll; l++) {
        k_ln<<<Tt, 256>>>(attn_g + (size_t)l * Dd, attn_b + (size_t)l * Dd);
        k_gemm_mma<<<dim3((3 * Dd) / 128, Tt / 128), 256, GEMM_SMEM>>>(
            pxnh, pxnl, pwqh, pwql, b_qkv, nullptr, pqkv, 3 * Dd, Dd);
        k_attn<<<dim3(Bb * Hh, Ss / 32), 256>>>();
        k_gemm_mma<<<dim3(Dd / 128, Tt / 128), 256, GEMM_SMEM>>>(
            path, patl, pwoh, pwol, b_out, px, px, Dd, Dd);
        k_ln<<<Tt, 256>>>(moe_g + (size_t)l * Dd, moe_b + (size_t)l * Dd);
        k_zero16<<<1, 16>>>();
        k_gate<<<Tt / 8, 256>>>(w_gate);
        k_route<<<1, 256>>>();
        k_moe_mma<<<dim3(Dd / 128, (CAPe + 127) / 128, NE), 256, GEMM_SMEM>>>(b_exp);
    }

    k_out<<<(out_size + 255) / 256, 256>>>((float*)d_out, out_size);
}

// round 7
// speedup vs baseline: 1.0669x; 1.0669x over previous
#include <cuda_runtime.h>
#include <math.h>
#include <stdint.h>

#define Bb 2
#define Ss 1024
#define Tt 2048
#define Dd 2048
#define Ll 4
#define NE 16
#define Hh 16
#define DHh 128
#define CAPe 153

typedef unsigned long long u64;

// ---------------- packed f32x2 helpers (sm_103a) ----------------------------
__device__ __forceinline__ void ffma2(u64& d, u64 a, u64 b) {
    asm("fma.rn.f32x2 %0, %1, %2, %0;" : "+l"(d) : "l"(a), "l"(b));
}
__device__ __forceinline__ u64 fmul2(u64 a, u64 b) {
    u64 r; asm("mul.rn.f32x2 %0, %1, %2;" : "=l"(r) : "l"(a), "l"(b)); return r;
}
__device__ __forceinline__ u64 pk2(float x, float y) {
    u64 r; asm("mov.b64 %0, {%1, %2};" : "=l"(r) : "f"(x), "f"(y)); return r;
}
__device__ __forceinline__ void upk2(u64 v, float& x, float& y) {
    asm("mov.b64 {%0, %1}, %2;" : "=f"(x), "=f"(y) : "l"(v));
}

// ---------------- tf32 helpers ----------------------------------------------
__device__ __forceinline__ float tf32r(float x) {
    uint32_t u; asm("cvt.rna.tf32.f32 %0, %1;" : "=r"(u) : "f"(x));
    return __uint_as_float(u);
}
// D += A * B  (m16n8k8, tf32 inputs, f32 accum). NOT volatile: pure register
// op; lets ptxas interleave independent MMAs to hide HMMA latency.
__device__ __forceinline__ void mma8(float* d, const uint32_t* a, const uint32_t* b) {
    asm("mma.sync.aligned.m16n8k8.row.col.f32.tf32.tf32.f32 "
        "{%0,%1,%2,%3}, {%4,%5,%6,%7}, {%8,%9}, {%0,%1,%2,%3};"
        : "+f"(d[0]), "+f"(d[1]), "+f"(d[2]), "+f"(d[3])
        : "r"(a[0]), "r"(a[1]), "r"(a[2]), "r"(a[3]), "r"(b[0]), "r"(b[1]));
}

// smem float offsets (stride 36 per row; 36 == 4 mod 32 -> conflict free)
#define AS_HI 0
#define AS_LO 4608
#define WS_HI 9216
#define WS_LO 11520
#define MMA_SMEM_FLOATS 13824
#define MMA_SMEM_BYTES  (MMA_SMEM_FLOATS * 4)

// ---------------- scratch (static device globals; no allocations) ----------
__device__ float g_x[Tt * Dd];
__device__ float g_xn[Tt * Dd];
__device__ float g_qkv[Tt * 3 * Dd];
__device__ float g_attn[Tt * Dd];
__device__ int   g_expert[Tt];
__device__ float g_prob[Tt];
__device__ float g_probsum[NE];
__device__ int   g_tok[NE * CAPe];
__device__ int   g_cnt[NE];
__device__ float g_aux;

__global__ void k_init() { g_aux = 0.0f; }
__global__ void k_zero16() { if (threadIdx.x < NE) g_probsum[threadIdx.x] = 0.0f; }

// ---------------- embedding gather ------------------------------------------
__global__ void k_embed(const int* __restrict__ tokens, const float* __restrict__ emb) {
    int idx = blockIdx.x * 256 + threadIdx.x;
    int t = idx / Dd;
    int d = idx % Dd;
    g_x[idx] = emb[(size_t)tokens[t] * Dd + d];
}

// ---------------- layernorm -------------------------------------------------
__global__ void k_ln(const float* __restrict__ gamma, const float* __restrict__ beta) {
    int t = blockIdx.x;
    const float* row = g_x + (size_t)t * Dd;
    float s = 0.f, s2 = 0.f;
    for (int d = threadIdx.x; d < Dd; d += 256) {
        float v = row[d];
        s += v; s2 += v * v;
    }
    #pragma unroll
    for (int o = 16; o; o >>= 1) {
        s  += __shfl_xor_sync(0xffffffffu, s, o);
        s2 += __shfl_xor_sync(0xffffffffu, s2, o);
    }
    __shared__ float shs[8], shs2[8];
    __shared__ float smu, srstd;
    int w = threadIdx.x >> 5, ln = threadIdx.x & 31;
    if (ln == 0) { shs[w] = s; shs2[w] = s2; }
    __syncthreads();
    if (threadIdx.x == 0) {
        float a = 0.f, b2 = 0.f;
        #pragma unroll
        for (int i = 0; i < 8; i++) { a += shs[i]; b2 += shs2[i]; }
        float m = a / (float)Dd;
        float var = b2 / (float)Dd - m * m;
        smu = m;
        srstd = rsqrtf(var + 1e-5f);
    }
    __syncthreads();
    float mu = smu, rstd = srstd;
    for (int d = threadIdx.x; d < Dd; d += 256)
        g_xn[(size_t)t * Dd + d] = (row[d] - mu) * rstd * gamma[d] + beta[d];
}

// ---------------- helpers for mma GEMM staging -------------------------------
__device__ __forceinline__ void split_store(float* sm, int hi_off, int lo_off,
                                            int pos, float4 v) {
    float4 h, l;
    h.x = tf32r(v.x); l.x = tf32r(v.x - h.x);
    h.y = tf32r(v.y); l.y = tf32r(v.y - h.y);
    h.z = tf32r(v.z); l.z = tf32r(v.z - h.z);
    h.w = tf32r(v.w); l.w = tf32r(v.w - h.w);
    *(float4*)(sm + hi_off + pos) = h;
    *(float4*)(sm + lo_off + pos) = l;
}

// inner compute: one BK=32 chunk, warp computes 32x32 via m16n8k8 x (2x4) x3.
// Term-outermost ordering: consecutive MMAs hit 8 distinct accumulator cells,
// so same-cell dependent MMAs are 8 issues apart (latency hidden).
__device__ __forceinline__ void mma_chunk(const float* sm, int wr, int wc,
                                          int grp, int qid, float acc[2][4][4]) {
    #pragma unroll
    for (int ks = 0; ks < 4; ks++) {
        int kc = ks * 8;
        uint32_t ahi[2][4], alo[2][4], bhi[4][2], blo[4][2];
        #pragma unroll
        for (int mi = 0; mi < 2; mi++) {
            int rb = wr * 32 + mi * 16;
            int i00 = (rb + grp) * 36 + kc + qid;
            int i10 = (rb + grp + 8) * 36 + kc + qid;
            ahi[mi][0] = *(const uint32_t*)(sm + AS_HI + i00);
            ahi[mi][1] = *(const uint32_t*)(sm + AS_HI + i10);
            ahi[mi][2] = *(const uint32_t*)(sm + AS_HI + i00 + 4);
            ahi[mi][3] = *(const uint32_t*)(sm + AS_HI + i10 + 4);
            alo[mi][0] = *(const uint32_t*)(sm + AS_LO + i00);
            alo[mi][1] = *(const uint32_t*)(sm + AS_LO + i10);
            alo[mi][2] = *(const uint32_t*)(sm + AS_LO + i00 + 4);
            alo[mi][3] = *(const uint32_t*)(sm + AS_LO + i10 + 4);
        }
        #pragma unroll
        for (int ni = 0; ni < 4; ni++) {
            int nb = wc * 32 + ni * 8;
            int i0 = (nb + grp) * 36 + kc + qid;
            bhi[ni][0] = *(const uint32_t*)(sm + WS_HI + i0);
            bhi[ni][1] = *(const uint32_t*)(sm + WS_HI + i0 + 4);
            blo[ni][0] = *(const uint32_t*)(sm + WS_LO + i0);
            blo[ni][1] = *(const uint32_t*)(sm + WS_LO + i0 + 4);
        }
        // term 1: hi*hi over all 8 cells
        #pragma unroll
        for (int mi = 0; mi < 2; mi++)
            #pragma unroll
            for (int ni = 0; ni < 4; ni++)
                mma8(acc[mi][ni], ahi[mi], bhi[ni]);
        // term 2: hi*lo
        #pragma unroll
        for (int mi = 0; mi < 2; mi++)
            #pragma unroll
            for (int ni = 0; ni < 4; ni++)
                mma8(acc[mi][ni], ahi[mi], blo[ni]);
        // term 3: lo*hi
        #pragma unroll
        for (int mi = 0; mi < 2; mi++)
            #pragma unroll
            for (int ni = 0; ni < 4; ni++)
                mma8(acc[mi][ni], alo[mi], bhi[ni]);
    }
}

// ---------------- dense GEMM: C[M,N] = A[M,K] @ W[N,K]^T + bias (+res) ------
// BM=128, BN=64, BK=32, 256 threads (8 warps 4x2), tf32 3x split mma.sync
__global__ void __launch_bounds__(256, 2)
k_gemm_mma(const float* __restrict__ A, const float* __restrict__ W,
           const float* __restrict__ bias, const float* __restrict__ res,
           float* __restrict__ C, int N, int K) {
    extern __shared__ float sm[];
    int tid = threadIdx.x, wid = tid >> 5, lane = tid & 31;
    int grp = lane >> 2, qid = lane & 3;
    int wr = wid & 3, wc = wid >> 2;
    int bm = blockIdx.y * 128, bn = blockIdx.x * 64;

    float acc[2][4][4];
    #pragma unroll
    for (int mi = 0; mi < 2; mi++)
        #pragma unroll
        for (int ni = 0; ni < 4; ni++)
            #pragma unroll
            for (int j = 0; j < 4; j++) acc[mi][ni][j] = 0.f;

    int rA[4], cA[4], posA[4];
    #pragma unroll
    for (int j = 0; j < 4; j++) {
        int idx = tid + j * 256;
        rA[j] = idx >> 3; cA[j] = (idx & 7) * 4;
        posA[j] = rA[j] * 36 + cA[j];
    }
    int rW[2], cW[2], posW[2];
    #pragma unroll
    for (int j = 0; j < 2; j++) {
        int idx = tid + j * 256;
        rW[j] = idx >> 3; cW[j] = (idx & 7) * 4;
        posW[j] = rW[j] * 36 + cW[j];
    }

    const float* Ab = A + (size_t)bm * K;
    const float* Wb = W + (size_t)bn * K;
    int nch = K / 32;

    float4 ra[4], rw[2];
    #pragma unroll
    for (int j = 0; j < 4; j++) ra[j] = *(const float4*)(Ab + (size_t)rA[j] * K + cA[j]);
    #pragma unroll
    for (int j = 0; j < 2; j++) rw[j] = *(const float4*)(Wb + (size_t)rW[j] * K + cW[j]);

    for (int c = 0; c < nch; c++) {
        #pragma unroll
        for (int j = 0; j < 4; j++) split_store(sm, AS_HI, AS_LO, posA[j], ra[j]);
        #pragma unroll
        for (int j = 0; j < 2; j++) split_store(sm, WS_HI, WS_LO, posW[j], rw[j]);
        __syncthreads();
        if (c + 1 < nch) {
            int k0 = (c + 1) * 32;
            #pragma unroll
            for (int j = 0; j < 4; j++) ra[j] = *(const float4*)(Ab + (size_t)rA[j] * K + k0 + cA[j]);
            #pragma unroll
            for (int j = 0; j < 2; j++) rw[j] = *(const float4*)(Wb + (size_t)rW[j] * K + k0 + cW[j]);
        }
        mma_chunk(sm, wr, wc, grp, qid, acc);
        __syncthreads();
    }

    #pragma unroll
    for (int mi = 0; mi < 2; mi++) {
        #pragma unroll
        for (int ni = 0; ni < 4; ni++) {
            int r0 = bm + wr * 32 + mi * 16 + grp;
            int r1 = r0 + 8;
            int cc = bn + wc * 32 + ni * 8 + qid * 2;
            float b0 = bias[cc], b1 = bias[cc + 1];
            float v0 = acc[mi][ni][0] + b0, v1 = acc[mi][ni][1] + b1;
            float v2 = acc[mi][ni][2] + b0, v3 = acc[mi][ni][3] + b1;
            if (res) {
                v0 += res[(size_t)r0 * N + cc];
                v1 += res[(size_t)r0 * N + cc + 1];
                v2 += res[(size_t)r1 * N + cc];
                v3 += res[(size_t)r1 * N + cc + 1];
            }
            C[(size_t)r0 * N + cc]     = v0;
            C[(size_t)r0 * N + cc + 1] = v1;
            C[(size_t)r1 * N + cc]     = v2;
            C[(size_t)r1 * N + cc + 1] = v3;
        }
    }
}

// ---------------- MoE GEMM (mma): x[t] += p*(h[t] @ We^T + be) --------------
__global__ void __launch_bounds__(256, 2)
k_moe_mma(const float* __restrict__ w_exp, const float* __restrict__ b_exp) {
    int e = blockIdx.z;
    int cnt = g_cnt[e];
    int row0 = blockIdx.y * 128;
    if (row0 >= cnt) return;
    int bn = blockIdx.x * 64;

    extern __shared__ float sm[];
    __shared__ int   toks[128];
    __shared__ float pb[128];
    int tid = threadIdx.x, wid = tid >> 5, lane = tid & 31;
    int grp = lane >> 2, qid = lane & 3;
    int wr = wid & 3, wc = wid >> 2;

    if (tid < 128) {
        int s = row0 + tid;
        if (s < cnt) {
            int t = g_tok[e * CAPe + s];
            toks[tid] = t;
            pb[tid] = g_prob[t];
        } else {
            toks[tid] = -1;
            pb[tid] = 0.f;
        }
    }
    __syncthreads();

    float acc[2][4][4];
    #pragma unroll
    for (int mi = 0; mi < 2; mi++)
        #pragma unroll
        for (int ni = 0; ni < 4; ni++)
            #pragma unroll
            for (int j = 0; j < 4; j++) acc[mi][ni][j] = 0.f;

    int rA[4], cA[4], posA[4], tA[4];
    #pragma unroll
    for (int j = 0; j < 4; j++) {
        int idx = tid + j * 256;
        rA[j] = idx >> 3; cA[j] = (idx & 7) * 4;
        posA[j] = rA[j] * 36 + cA[j];
        tA[j] = toks[rA[j]];
    }
    int rW[2], cW[2], posW[2];
    #pragma unroll
    for (int j = 0; j < 2; j++) {
        int idx = tid + j * 256;
        rW[j] = idx >> 3; cW[j] = (idx & 7) * 4;
        posW[j] = rW[j] * 36 + cW[j];
    }

    const float* Wb = w_exp + (size_t)e * Dd * Dd + (size_t)bn * Dd;
    const int nch = Dd / 32;

    float4 ra[4], rw[2];
    #pragma unroll
    for (int j = 0; j < 4; j++)
        ra[j] = (tA[j] >= 0) ? *(const float4*)(g_xn + (size_t)tA[j] * Dd + cA[j])
                             : make_float4(0.f, 0.f, 0.f, 0.f);
    #pragma unroll
    for (int j = 0; j < 2; j++) rw[j] = *(const float4*)(Wb + (size_t)rW[j] * Dd + cW[j]);

    for (int c = 0; c < nch; c++) {
        #pragma unroll
        for (int j = 0; j < 4; j++) split_store(sm, AS_HI, AS_LO, posA[j], ra[j]);
        #pragma unroll
        for (int j = 0; j < 2; j++) split_store(sm, WS_HI, WS_LO, posW[j], rw[j]);
        __syncthreads();
        if (c + 1 < nch) {
            int k0 = (c + 1) * 32;
            #pragma unroll
            for (int j = 0; j < 4; j++)
                ra[j] = (tA[j] >= 0) ? *(const float4*)(g_xn + (size_t)tA[j] * Dd + k0 + cA[j])
                                     : make_float4(0.f, 0.f, 0.f, 0.f);
            #pragma unroll
            for (int j = 0; j < 2; j++) rw[j] = *(const float4*)(Wb + (size_t)rW[j] * Dd + k0 + cW[j]);
        }
        mma_chunk(sm, wr, wc, grp, qid, acc);
        __syncthreads();
    }

    const float* be = b_exp + (size_t)e * Dd;
    #pragma unroll
    for (int mi = 0; mi < 2; mi++) {
        int lr0 = wr * 32 + mi * 16 + grp;
        int lr1 = lr0 + 8;
        int s0 = row0 + lr0, s1 = row0 + lr1;
        #pragma unroll
        for (int ni = 0; ni < 4; ni++) {
            int cc = bn + wc * 32 + ni * 8 + qid * 2;
            float b0 = be[cc], b1 = be[cc + 1];
            if (s0 < cnt) {
                int t = toks[lr0]; float p = pb[lr0];
                g_x[(size_t)t * Dd + cc]     += p * (acc[mi][ni][0] + b0);
                g_x[(size_t)t * Dd + cc + 1] += p * (acc[mi][ni][1] + b1);
            }
            if (s1 < cnt) {
                int t = toks[lr1]; float p = pb[lr1];
                g_x[(size_t)t * Dd + cc]     += p * (acc[mi][ni][2] + b0);
                g_x[(size_t)t * Dd + cc + 1] += p * (acc[mi][ni][3] + b1);
            }
        }
    }
}

// ---------------- attention (flash-style, BQ=32, BKV=32, packed fma) --------
__global__ void __launch_bounds__(256, 2) k_attn() {
    int bh = blockIdx.x;
    int b = bh >> 4, h = bh & 15;
    int q0 = blockIdx.y * 32;
    __shared__ float Qs[32][132];
    __shared__ float KVs[32][132];
    __shared__ float Sc[32][36];
    int tid = threadIdx.x;

    #pragma unroll
    for (int j = 0; j < 4; j++) {
        int i = tid + j * 256;
        int r = i >> 5, d4 = (i & 31) << 2;
        float4 v = *(const float4*)&g_qkv[(size_t)(b * Ss + q0 + r) * (3 * Dd) + h * DHh + d4];
        *(float4*)&Qs[r][d4] = v;
    }

    int q  = tid >> 3;
    int dp = tid & 7;
    float m = -1e30f, l = 0.f;
    u64 acc2[8];
    #pragma unroll
    for (int j = 0; j < 8; j++) acc2[j] = 0ULL;

    const float scale = 0.08838834764831845f;

    for (int kb = 0; kb < Ss; kb += 32) {
        __syncthreads();
        #pragma unroll
        for (int j = 0; j < 4; j++) {
            int i = tid + j * 256;
            int r = i >> 5, d4 = (i & 31) << 2;
            float4 v = *(const float4*)&g_qkv[(size_t)(b * Ss + kb + r) * (3 * Dd) + Dd + h * DHh + d4];
            *(float4*)&KVs[r][d4] = v;
        }
        __syncthreads();
        {
            u64 s2[4] = {0ULL, 0ULL, 0ULL, 0ULL};
            #pragma unroll
            for (int ch = 0; ch < 8; ch++) {
                ulonglong2 qa = *(const ulonglong2*)&Qs[q][ch * 16];
                ulonglong2 qb = *(const ulonglong2*)&Qs[q][ch * 16 + 4];
                ulonglong2 qc = *(const ulonglong2*)&Qs[q][ch * 16 + 8];
                ulonglong2 qd = *(const ulonglong2*)&Qs[q][ch * 16 + 12];
                #pragma unroll
                for (int kk = 0; kk < 4; kk++) {
                    int k = dp + kk * 8;
                    ulonglong2 ka = *(const ulonglong2*)&KVs[k][ch * 16];
                    ulonglong2 kb2 = *(const ulonglong2*)&KVs[k][ch * 16 + 4];
                    ulonglong2 kc = *(const ulonglong2*)&KVs[k][ch * 16 + 8];
                    ulonglong2 kd = *(const ulonglong2*)&KVs[k][ch * 16 + 12];
                    ffma2(s2[kk], qa.x, ka.x);
                    ffma2(s2[kk], qa.y, ka.y);
                    ffma2(s2[kk], qb.x, kb2.x);
                    ffma2(s2[kk], qb.y, kb2.y);
                    ffma2(s2[kk], qc.x, kc.x);
                    ffma2(s2[kk], qc.y, kc.y);
                    ffma2(s2[kk], qd.x, kd.x);
                    ffma2(s2[kk], qd.y, kd.y);
                }
            }
            #pragma unroll
            for (int kk = 0; kk < 4; kk++) {
                float lo, hi; upk2(s2[kk], lo, hi);
                Sc[q][dp + kk * 8] = (lo + hi) * scale;
            }
        }
        __syncthreads();
        #pragma unroll
        for (int j = 0; j < 4; j++) {
            int i = tid + j * 256;
            int r = i >> 5, d4 = (i & 31) << 2;
            float4 v = *(const float4*)&g_qkv[(size_t)(b * Ss + kb + r) * (3 * Dd) + 2 * Dd + h * DHh + d4];
            *(float4*)&KVs[r][d4] = v;
        }
        float sc[32];
        #pragma unroll
        for (int k = 0; k < 32; k++) sc[k] = Sc[q][k];
        float mx = -1e30f;
        #pragma unroll
        for (int k = 0; k < 32; k++) mx = fmaxf(mx, sc[k]);
        float nm = fmaxf(m, mx);
        float corr = __expf(m - nm);
        l *= corr;
        u64 cp = pk2(corr, corr);
        #pragma unroll
        for (int j = 0; j < 8; j++) acc2[j] = fmul2(acc2[j], cp);
        float p[32];
        #pragma unroll
        for (int k = 0; k < 32; k++) { p[k] = __expf(sc[k] - nm); l += p[k]; }
        m = nm;
        __syncthreads();
        #pragma unroll
        for (int k = 0; k < 32; k++) {
            u64 pp = pk2(p[k], p[k]);
            ulonglong2 v0 = *(const ulonglong2*)&KVs[k][dp * 16];
            ulonglong2 v1 = *(const ulonglong2*)&KVs[k][dp * 16 + 4];
            ulonglong2 v2 = *(const ulonglong2*)&KVs[k][dp * 16 + 8];
            ulonglong2 v3 = *(const ulonglong2*)&KVs[k][dp * 16 + 12];
            ffma2(acc2[0], pp, v0.x);
            ffma2(acc2[1], pp, v0.y);
            ffma2(acc2[2], pp, v1.x);
            ffma2(acc2[3], pp, v1.y);
            ffma2(acc2[4], pp, v2.x);
            ffma2(acc2[5], pp, v2.y);
            ffma2(acc2[6], pp, v3.x);
            ffma2(acc2[7], pp, v3.y);
        }
    }
    float inv = 1.f / l;
    int t = b * Ss + q0 + q;
    float* op = g_attn + (size_t)t * Dd + h * DHh + dp * 16;
    float o[16];
    upk2(acc2[0], o[0],  o[1]);   upk2(acc2[1], o[2],  o[3]);
    upk2(acc2[2], o[4],  o[5]);   upk2(acc2[3], o[6],  o[7]);
    upk2(acc2[4], o[8],  o[9]);   upk2(acc2[5], o[10], o[11]);
    upk2(acc2[6], o[12], o[13]);  upk2(acc2[7], o[14], o[15]);
    #pragma unroll
    for (int j = 0; j < 16; j++) op[j] = o[j] * inv;
}

// ---------------- gate ------------------------------------------------------
__global__ void k_gate(const float* __restrict__ wg) {
    int warp = threadIdx.x >> 5;
    int lane = threadIdx.x & 31;
    int t = blockIdx.x * 8 + warp;
    __shared__ float bsum[NE];
    if (threadIdx.x < NE) bsum[threadIdx.x] = 0.f;
    __syncthreads();

    float lg[16];
    #pragma unroll
    for (int e = 0; e < 16; e++) lg[e] = 0.f;
    const float* row = g_xn + (size_t)t * Dd;
    for (int d = lane; d < Dd; d += 32) {
        float x = row[d];
        const float* w = wg + (size_t)d * NE;
        #pragma unroll
        for (int e = 0; e < 16; e++) lg[e] += x * w[e];
    }
    #pragma unroll
    for (int e = 0; e < 16; e++)
        #pragma unroll
        for (int o = 16; o; o >>= 1) lg[e] += __shfl_xor_sync(0xffffffffu, lg[e], o);

    float mx = lg[0];
    #pragma unroll
    for (int e = 1; e < 16; e++) mx = fmaxf(mx, lg[e]);
    float pe[16]; float se = 0.f;
    #pragma unroll
    for (int e = 0; e < 16; e++) { pe[e] = __expf(lg[e] - mx); se += pe[e]; }
    float inv = 1.f / se;

    if (lane == 0) {
        int be = 0; float bl = lg[0];
        #pragma unroll
        for (int e = 1; e < 16; e++) if (lg[e] > bl) { bl = lg[e]; be = e; }
        g_expert[t] = be;
        g_prob[t] = pe[be] * inv;
        #pragma unroll
        for (int e = 0; e < 16; e++) atomicAdd(&bsum[e], pe[e] * inv);
    }
    __syncthreads();
    if (threadIdx.x < NE) atomicAdd(&g_probsum[threadIdx.x], bsum[threadIdx.x]);
}

// ---------------- routing ---------------------------------------------------
__global__ void k_route() {
    __shared__ int sh_e[Tt];
    __shared__ int cnts[256][NE];
    __shared__ int tot[NE];
    int tid = threadIdx.x;
    for (int i = tid; i < Tt; i += 256) sh_e[i] = g_expert[i];
    #pragma unroll
    for (int e = 0; e < NE; e++) cnts[tid][e] = 0;
    __syncthreads();
    for (int i = 0; i < 8; i++) {
        int e = sh_e[tid * 8 + i];
        cnts[tid][e]++;
    }
    __syncthreads();
    if (tid < NE) {
        int run = 0;
        for (int i = 0; i < 256; i++) {
            int c = cnts[i][tid];
            cnts[i][tid] = run;
            run += c;
        }
        tot[tid] = run;
        g_cnt[tid] = (run < CAPe) ? run : CAPe;
    }
    __syncthreads();
    for (int i = 0; i < 8; i++) {
        int t = tid * 8 + i;
        int e = sh_e[t];
        int r = cnts[tid][e]++;
        if (r < CAPe) g_tok[e * CAPe + r] = t;
    }
    if (tid == 0) {
        float a = 0.f;
        for (int e = 0; e < NE; e++) a += (float)tot[e] * g_probsum[e];
        g_aux += a * ((float)NE / ((float)Tt * (float)Tt));
    }
}

// ---------------- output ----------------------------------------------------
__global__ void k_out(float* __restrict__ out, int n) {
    int idx = blockIdx.x * 256 + threadIdx.x;
    if (idx < n) {
        if (idx < Tt * Dd) out[idx] = g_x[idx];
        else out[idx] = g_aux;
    }
}

// ---------------- launch ----------------------------------------------------
extern "C" void kernel_launch(void* const* d_in, const int* in_sizes, int n_in,
                              void* d_out, int out_size) {
    const int*   tokens = (const int*)d_in[0];
    const float* emb    = (const float*)d_in[1];
    const float* w_qkv  = (const float*)d_in[2];
    const float* b_qkv  = (const float*)d_in[3];
    const float* w_out  = (const float*)d_in[4];
    const float* b_out  = (const float*)d_in[5];
    const float* attn_g = (const float*)d_in[6];
    const float* attn_b = (const float*)d_in[7];
    const float* moe_g  = (const float*)d_in[8];
    const float* moe_b  = (const float*)d_in[9];
    const float* w_gate = (const float*)d_in[10];
    const float* w_exp  = (const float*)d_in[11];
    const float* b_exp  = (const float*)d_in[12];

    float *px, *pxn, *pqkv, *pattn;
    cudaGetSymbolAddress((void**)&px, g_x);
    cudaGetSymbolAddress((void**)&pxn, g_xn);
    cudaGetSymbolAddress((void**)&pqkv, g_qkv);
    cudaGetSymbolAddress((void**)&pattn, g_attn);

    cudaFuncSetAttribute(k_gemm_mma, cudaFuncAttributeMaxDynamicSharedMemorySize, MMA_SMEM_BYTES);
    cudaFuncSetAttribute(k_moe_mma, cudaFuncAttributeMaxDynamicSharedMemorySize, MMA_SMEM_BYTES);

    k_init<<<1, 1>>>();
    k_embed<<<(Tt * Dd) / 256, 256>>>(tokens, emb);

    for (int l = 0; l < Ll; l++) {
        k_ln<<<Tt, 256>>>(attn_g + (size_t)l * Dd, attn_b + (size_t)l * Dd);
        k_gemm_mma<<<dim3((3 * Dd) / 64, Tt / 128), 256, MMA_SMEM_BYTES>>>(
            pxn, w_qkv, b_qkv, nullptr, pqkv, 3 * Dd, Dd);
        k_attn<<<dim3(Bb * Hh, Ss / 32), 256>>>();
        k_gemm_mma<<<dim3(Dd / 64, Tt / 128), 256, MMA_SMEM_BYTES>>>(
            pattn, w_out, b_out, px, px, Dd, Dd);
        k_ln<<<Tt, 256>>>(moe_g + (size_t)l * Dd, moe_b + (size_t)l * Dd);
        k_zero16<<<1, 16>>>();
        k_gate<<<Tt / 8, 256>>>(w_gate);
        k_route<<<1, 256>>>();
        k_moe_mma<<<dim3(Dd / 64, (CAPe + 127) / 128, NE), 256, MMA_SMEM_BYTES>>>(w_exp, b_exp);
    }

    k_out<<<(out_size + 255) / 256, 256>>>((float*)d_out, out_size);
}